// round 12
// baseline (speedup 1.0000x reference)
#include <cuda_runtime.h>
#include <cuda_bf16.h>
#include <cstddef>
#include <stdint.h>
#include <math.h>

#define BATCH 256
#define TT    2048
#define HID   128
#define G4    512           // 4*HID
#define MROWS (BATCH*TT)    // 524288

typedef unsigned long long ull;

// ---- scratch (static device arrays: sanctioned allocation-free path) ----
__device__ float g_out0[(size_t)MROWS * HID];   // layer0 hidden states [B*T, 128]
__device__ float g_xg1 [(size_t)MROWS * G4];    // layer1 input gates (+bias) [B*T, 512]

// ---------------- packed f32x2 helpers (sm_103a) ----------------
__device__ __forceinline__ ull pk2(float lo, float hi) {
    ull r; asm("mov.b64 %0, {%1, %2};" : "=l"(r) : "f"(lo), "f"(hi)); return r;
}
__device__ __forceinline__ float2 upk(ull v) {
    float2 r; asm("mov.b64 {%0, %1}, %2;" : "=f"(r.x), "=f"(r.y) : "l"(v)); return r;
}
__device__ __forceinline__ void ffma2(ull& d, ull a, ull b) {
    asm("fma.rn.f32x2 %0, %1, %2, %0;" : "+l"(d) : "l"(a), "l"(b));
}

// ---------------- fast activations ----------------
__device__ __forceinline__ float sigm_f(float v) {
    float e = __expf(-v);
    return __fdividef(1.0f, 1.0f + e);    // inf -> 0, 0 -> 1 : correct tails
}
__device__ __forceinline__ float tanh_f(float v) {
    float e = __expf(2.0f * v);           // 0 -> -1, inf -> +1 : correct tails
    return 1.0f - __fdividef(2.0f, 1.0f + e);
}

// ---------------- tf32 helpers ----------------
__device__ __forceinline__ uint32_t cvt_tf32(float f) {
    uint32_t r; asm("cvt.rna.tf32.f32 %0, %1;" : "=r"(r) : "f"(f)); return r;
}
__device__ __forceinline__ void mma_tf32(float* c, uint4 a, uint32_t b0, uint32_t b1) {
    asm volatile("mma.sync.aligned.m16n8k8.row.col.f32.tf32.tf32.f32 "
        "{%0,%1,%2,%3}, {%4,%5,%6,%7}, {%8,%9}, {%0,%1,%2,%3};"
        : "+f"(c[0]), "+f"(c[1]), "+f"(c[2]), "+f"(c[3])
        : "r"(a.x), "r"(a.y), "r"(a.z), "r"(a.w), "r"(b0), "r"(b1));
}

extern __shared__ __align__(16) unsigned char dynsm[];

// ---------------------------------------------------------------------------
// LSTM layer — 128 CTAs x 512 threads (16 warps, 4/SMSP: 2x R11 occupancy).
// CTA owns batch rows 2*bx, 2*bx+1. Thread owns ONE gate row r = tid for
// BOTH batch rows -> 2 dots/thread/step.
// Row weights: floats [0,72) in 18 float4-chunk registers (72 regs),
//              floats [72,128) in smem, k-major [14][512] (conflict-free LDS.128).
// xg contribution: LDGs issued pre-dot, ADDED POST-DOT (accumulators seed 0)
// -> no DRAM-latency chain at the head of the dot (the R11 lstm1 stall).
// Two __syncthreads per step.
// ---------------------------------------------------------------------------
#define WREGC 18                       // reg chunks (4 floats each)
#define WSMC  (32 - WREGC)             // 14 smem chunks
#define SMEM_LSTM (WSMC*512*16 /*Wsm*/ + 2*HID*4 /*h*/ + 2*G4*4 /*gates*/)

template<int LAYER>
__global__ void __launch_bounds__(512, 1)
lstm_kernel(const float* __restrict__ x,     // layer0: [B,T,1]
            const float* __restrict__ W_ih,  // layer0: [512,1]
            const float* __restrict__ W_hh,  // [512,128]
            const float* __restrict__ b_ih,
            const float* __restrict__ b_hh,
            const float* __restrict__ W_fc,  // layer1: [1,128]
            const float* __restrict__ b_fc,  // layer1: [1]
            float* __restrict__ out)
{
    ulonglong2* Wsm    = (ulonglong2*)dynsm;               // [14][512]
    float*      h_sm   = (float*)(dynsm + WSMC*512*16);    // [2][128]
    float*      gate_sm= h_sm + 2 * HID;                   // [2][512]

    const int tid = threadIdx.x;
    const int b0  = blockIdx.x * 2;
    const int r   = tid;                    // gate row 0..511
    const int gcls= tid >> 7;               // 0:i 1:f 2:g 3:o (warp-uniform)

    // ---- weight staging: chunks [0,18) -> regs, [18,32) -> smem ----
    ulonglong2 wreg[WREGC];
    {
        const ulonglong2* wp = (const ulonglong2*)(W_hh + (size_t)r * HID);
        #pragma unroll
        for (int q = 0; q < WREGC; q++)
            wreg[q] = wp[q];
        #pragma unroll
        for (int q = 0; q < WSMC; q++)
            Wsm[q * 512 + tid] = wp[WREGC + q];
    }

    float wih = 0.f, bias = 0.f;
    if (LAYER == 0) {
        wih  = __ldg(&W_ih[r]);
        bias = __ldg(&b_ih[r]) + __ldg(&b_hh[r]);
    }

    if (tid < 2 * HID) h_sm[tid] = 0.f;
    float c = 0.f;                          // cell state (threads < 256 own it)
    __syncthreads();

    const ulonglong2* hp0 = (const ulonglong2*)h_sm;          // 32 chunks
    const ulonglong2* hp1 = (const ulonglong2*)(h_sm + HID);
    const int ub = (tid >> 7) & 1;          // update thread (tid<256): batch slot
    const int uj = tid & (HID - 1);         // hidden index

    for (int t = 0; t < TT; t++) {
        // --- xg loads: issue now, consume AFTER the dot ---
        float xga, xgb;
        if (LAYER == 0) {
            float xv0 = __ldg(&x[(size_t)b0 * TT + t]);
            float xv1 = __ldg(&x[(size_t)(b0 + 1) * TT + t]);
            xga = fmaf(wih, xv0, bias);
            xgb = fmaf(wih, xv1, bias);
        } else {
            xga = __ldg(&g_xg1[((size_t)b0 * TT + t) * G4 + r]);
            xgb = __ldg(&g_xg1[((size_t)(b0 + 1) * TT + t) * G4 + r]);
        }

        // --- 2 dots of length 128 (batch rows b0, b0+1), K-packed f32x2 ---
        ull a0 = pk2(0.f, 0.f), a1 = pk2(0.f, 0.f);   // batch 0, 2 chains
        ull b0a = pk2(0.f, 0.f), b1a = pk2(0.f, 0.f); // batch 1, 2 chains

        #pragma unroll
        for (int q = 0; q < WREGC; q++) {
            ulonglong2 h0 = hp0[q];
            ulonglong2 h1 = hp1[q];
            ulonglong2 w  = wreg[q];
            ffma2(a0,  w.x, h0.x); ffma2(a1,  w.y, h0.y);
            ffma2(b0a, w.x, h1.x); ffma2(b1a, w.y, h1.y);
        }
        #pragma unroll
        for (int q = 0; q < WSMC; q++) {
            ulonglong2 h0 = hp0[WREGC + q];
            ulonglong2 h1 = hp1[WREGC + q];
            ulonglong2 w  = Wsm[q * 512 + tid];
            ffma2(a0,  w.x, h0.x); ffma2(a1,  w.y, h0.y);
            ffma2(b0a, w.x, h1.x); ffma2(b1a, w.y, h1.y);
        }

        float2 u;
        u = upk(a0);  float sa = u.x + u.y;
        u = upk(a1);  sa += u.x + u.y; sa += xga;
        u = upk(b0a); float sb = u.x + u.y;
        u = upk(b1a); sb += u.x + u.y; sb += xgb;

        // --- activation (warp-uniform branch): g-rows tanh, others sigmoid ---
        float ga, gb;
        if (gcls == 2) { ga = tanh_f(sa); gb = tanh_f(sb); }
        else           { ga = sigm_f(sa); gb = sigm_f(sb); }

        gate_sm[r]       = ga;
        gate_sm[G4 + r]  = gb;
        __syncthreads();

        // --- cell/hidden update: threads 0..255, thread owns (ub, uj) ---
        if (tid < 2 * HID) {
            const float* gb_ = gate_sm + ub * G4;
            float iv = gb_[uj];
            float fv = gb_[HID + uj];
            float gv = gb_[2 * HID + uj];
            float ov = gb_[3 * HID + uj];
            c = fmaf(fv, c, iv * gv);
            float h = ov * tanh_f(c);
            h_sm[tid] = h;                        // tid == ub*HID + uj
            if (LAYER == 0)
                g_out0[((size_t)(b0 + ub) * TT + t) * HID + uj] = h;
        }
        __syncthreads();
    }

    // --- finals. out: y[256] | h_n[2][256][128] | c_n[2][256][128] ---
    if (tid < 2 * HID) {
        int bglob = b0 + ub;
        out[256 + ((size_t)LAYER * BATCH + bglob) * HID + uj] = h_sm[tid];
        out[256 + (size_t)2 * BATCH * HID
                + ((size_t)LAYER * BATCH + bglob) * HID + uj] = c;
    }

    // --- FC head (layer 1 only): y[b] = h_final[b] . W_fc + b_fc ---
    if (LAYER == 1 && tid < 64) {
        int w = tid >> 5;          // batch slot 0/1
        int l = tid & 31;
        float s = 0.f;
        #pragma unroll
        for (int q = l; q < HID; q += 32)
            s = fmaf(h_sm[w * HID + q], __ldg(&W_fc[q]), s);
        #pragma unroll
        for (int off = 16; off > 0; off >>= 1)
            s += __shfl_down_sync(0xffffffffu, s, off);
        if (l == 0)
            out[b0 + w] = s + __ldg(&b_fc[0]);
    }
}

// ---------------------------------------------------------------------------
// tf32 tensor-core GEMM (unchanged from R11, correctness-verified):
// g_xg1[M,512] = g_out0[M,128] @ W_ih1^T + bias
// ---------------------------------------------------------------------------
#define ASW_U (16*8*32*4)     // 16384 uints
#define BSW_U (16*32*20)      // 10240 uints
#define SMEM_GEMM ((ASW_U + BSW_U + 64) * 4)   // 106752 B

__global__ void __launch_bounds__(256, 2)
gemm_xg1_kernel(const float* __restrict__ W,     // W_ih_l1 [512,128]
                const float* __restrict__ b_ih,
                const float* __restrict__ b_hh)
{
    uint32_t* Asw    = (uint32_t*)dynsm;
    uint32_t* Bsw    = Asw + ASW_U;
    float*    bias_s = (float*)(Bsw + BSW_U);

    const int tid = threadIdx.x;
    const int n0  = blockIdx.x * 64;
    const int m0  = blockIdx.y * 128;

    if (tid < 64)
        bias_s[tid] = __ldg(&b_ih[n0 + tid]) + __ldg(&b_hh[n0 + tid]);

    // ---- stage A (128m x 128k): row-major global -> fragment order ----
    {
        const int row = tid >> 1;             // 0..127
        const int kh  = (tid & 1) * 64;       // k half
        const int w   = row >> 4;
        const int g   = row & 7;
        const int rb  = (row >> 3) & 1;       // row g vs g+8 within m16 tile
        const float4* ap = (const float4*)(g_out0 + (size_t)(m0 + row) * HID + kh);
        #pragma unroll
        for (int q = 0; q < 16; q++) {
            float4 v = ap[q];
            int k  = kh + q * 4;
            int s  = k >> 3;
            int kb = (k >> 2) & 1;
            uint32_t* dst = &Asw[(((s * 8 + w) * 32) + g * 4) * 4 + (rb + kb * 2)];
            dst[0]  = cvt_tf32(v.x);
            dst[4]  = cvt_tf32(v.y);
            dst[8]  = cvt_tf32(v.z);
            dst[12] = cvt_tf32(v.w);
        }
    }
    // ---- stage B (64n x 128k): W rows n0..n0+63 -> fragment order ----
    {
        const int bn  = tid & 63;             // n row
        const int kh  = (tid >> 6) * 32;      // k segment of 32
        const int nt  = bn >> 3;
        const int gg  = bn & 7;
        const float4* bp = (const float4*)(W + (size_t)(n0 + bn) * HID + kh);
        #pragma unroll
        for (int q = 0; q < 8; q++) {
            float4 v = bp[q];
            int k  = kh + q * 4;
            int s  = k >> 3;
            int kb = (k >> 2) & 1;
            uint32_t* dst = &Bsw[(s * 32 + gg * 4) * 20 + nt * 2 + kb];
            dst[0]  = cvt_tf32(v.x);
            dst[20] = cvt_tf32(v.y);
            dst[40] = cvt_tf32(v.z);
            dst[60] = cvt_tf32(v.w);
        }
    }
    __syncthreads();

    // ---- compute: warp w, lane l ----
    const int w = tid >> 5;
    const int l = tid & 31;

    float acc[8][4];
    #pragma unroll
    for (int i = 0; i < 8; i++)
        #pragma unroll
        for (int j = 0; j < 4; j++) acc[i][j] = 0.f;

    #pragma unroll
    for (int s = 0; s < 16; s++) {
        uint4 a = *(const uint4*)&Asw[((s * 8 + w) * 32 + l) * 4];
        const uint32_t* bb = &Bsw[(s * 32 + l) * 20];
        uint4 b0 = *(const uint4*)(bb + 0);
        uint4 b1 = *(const uint4*)(bb + 4);
        uint4 b2 = *(const uint4*)(bb + 8);
        uint4 b3 = *(const uint4*)(bb + 12);
        mma_tf32(acc[0], a, b0.x, b0.y); mma_tf32(acc[1], a, b0.z, b0.w);
        mma_tf32(acc[2], a, b1.x, b1.y); mma_tf32(acc[3], a, b1.z, b1.w);
        mma_tf32(acc[4], a, b2.x, b2.y); mma_tf32(acc[5], a, b2.z, b2.w);
        mma_tf32(acc[6], a, b3.x, b3.y); mma_tf32(acc[7], a, b3.z, b3.w);
    }

    // ---- epilogue ----
    const int g   = l >> 2;
    const int tig = l & 3;
    const size_t row0 = (size_t)(m0 + w * 16 + g);
    #pragma unroll
    for (int nt = 0; nt < 8; nt++) {
        int colb = nt * 8 + tig * 2;
        float bv0 = bias_s[colb], bv1 = bias_s[colb + 1];
        *(float2*)&g_xg1[row0 * G4 + n0 + colb] =
            make_float2(acc[nt][0] + bv0, acc[nt][1] + bv1);
        *(float2*)&g_xg1[(row0 + 8) * G4 + n0 + colb] =
            make_float2(acc[nt][2] + bv0, acc[nt][3] + bv1);
    }
}

// ---------------------------------------------------------------------------
// Launch
// ---------------------------------------------------------------------------
extern "C" void kernel_launch(void* const* d_in, const int* in_sizes, int n_in,
                              void* d_out, int out_size)
{
    const float* x      = (const float*)d_in[0];   // [256,2048,1]
    const float* W_ih0  = (const float*)d_in[1];   // [512,1]
    const float* W_hh0  = (const float*)d_in[2];   // [512,128]
    const float* b_ih0  = (const float*)d_in[3];
    const float* b_hh0  = (const float*)d_in[4];
    const float* W_ih1  = (const float*)d_in[5];   // [512,128]
    const float* W_hh1  = (const float*)d_in[6];   // [512,128]
    const float* b_ih1  = (const float*)d_in[7];
    const float* b_hh1  = (const float*)d_in[8];
    const float* W_fc   = (const float*)d_in[9];   // [1,128]
    const float* b_fc   = (const float*)d_in[10];  // [1]
    float* out = (float*)d_out;

    cudaFuncSetAttribute(lstm_kernel<0>, cudaFuncAttributeMaxDynamicSharedMemorySize, SMEM_LSTM);
    cudaFuncSetAttribute(lstm_kernel<1>, cudaFuncAttributeMaxDynamicSharedMemorySize, SMEM_LSTM);
    cudaFuncSetAttribute(gemm_xg1_kernel, cudaFuncAttributeMaxDynamicSharedMemorySize, SMEM_GEMM);

    // Layer 0 recurrence (writes g_out0, h_n[0], c_n[0])
    lstm_kernel<0><<<BATCH/2, 512, SMEM_LSTM>>>(
        x, W_ih0, W_hh0, b_ih0, b_hh0, nullptr, nullptr, out);

    // Layer 1 input gates: g_xg1 = g_out0 @ W_ih1^T + bias  (tf32 tensor cores)
    {
        dim3 grid(G4 / 64, MROWS / 128);
        gemm_xg1_kernel<<<grid, 256, SMEM_GEMM>>>(W_ih1, b_ih1, b_hh1);
    }

    // Layer 1 recurrence (reads g_xg1; writes h_n[1], c_n[1], y)
    lstm_kernel<1><<<BATCH/2, 512, SMEM_LSTM>>>(
        nullptr, nullptr, W_hh1, b_ih1, b_hh1, W_fc, b_fc, out);
}

// round 13
// speedup vs baseline: 1.1965x; 1.1965x over previous
#include <cuda_runtime.h>
#include <cuda_bf16.h>
#include <cstddef>
#include <stdint.h>
#include <math.h>

#define BATCH 256
#define TT    2048
#define HID   128
#define G4    512           // 4*HID
#define MROWS (BATCH*TT)    // 524288

typedef unsigned long long ull;

// ---- scratch (static device arrays: sanctioned allocation-free path) ----
__device__ float g_out0[(size_t)MROWS * HID];   // layer0 hidden states [B*T, 128]
__device__ float g_xg1 [(size_t)MROWS * G4];    // layer1 input gates (+bias) [B*T, 512]

// ---------------- packed f32x2 helpers (sm_103a) ----------------
__device__ __forceinline__ ull pk2(float lo, float hi) {
    ull r; asm("mov.b64 %0, {%1, %2};" : "=l"(r) : "f"(lo), "f"(hi)); return r;
}
__device__ __forceinline__ float2 upk(ull v) {
    float2 r; asm("mov.b64 {%0, %1}, %2;" : "=f"(r.x), "=f"(r.y) : "l"(v)); return r;
}
__device__ __forceinline__ void ffma2(ull& d, ull a, ull b) {
    asm("fma.rn.f32x2 %0, %1, %2, %0;" : "+l"(d) : "l"(a), "l"(b));
}

// ---------------- fast activations ----------------
__device__ __forceinline__ float sigm_f(float v) {
    float e = __expf(-v);
    return __fdividef(1.0f, 1.0f + e);    // inf -> 0, 0 -> 1 : correct tails
}
__device__ __forceinline__ float tanh_f(float v) {
    float e = __expf(2.0f * v);           // 0 -> -1, inf -> +1 : correct tails
    return 1.0f - __fdividef(2.0f, 1.0f + e);
}

// ---------------- tf32 helpers ----------------
__device__ __forceinline__ uint32_t cvt_tf32(float f) {
    uint32_t r; asm("cvt.rna.tf32.f32 %0, %1;" : "=r"(r) : "f"(f)); return r;
}
__device__ __forceinline__ void mma_tf32(float* c, uint4 a, uint32_t b0, uint32_t b1) {
    asm volatile("mma.sync.aligned.m16n8k8.row.col.f32.tf32.tf32.f32 "
        "{%0,%1,%2,%3}, {%4,%5,%6,%7}, {%8,%9}, {%0,%1,%2,%3};"
        : "+f"(c[0]), "+f"(c[1]), "+f"(c[2]), "+f"(c[3])
        : "r"(a.x), "r"(a.y), "r"(a.z), "r"(a.w), "r"(b0), "r"(b1));
}

extern __shared__ __align__(16) unsigned char dynsm[];

// ---------------------------------------------------------------------------
// LSTM layer — R8/R11 structure (measured 2714us for layer 0).
// 128 CTAs x 256 threads; CTA owns batch rows 2*bx, 2*bx+1.
// Thread owns gate rows r0 = tid (weights in SMEM, k-major ulonglong2,
// conflict-free LDS.128) and r1 = tid+256 (weights fully in 128 registers),
// for BOTH batch rows -> 4 dots/thread/step. Two __syncthreads per step.
//
// R13 change (LAYER==1 only): xg is software-pipelined. xg(t+1) LDGs are
// issued during step t's dot; accumulators seed with 0 and the current xg
// is added POST-dot. This removes the ~600-900cyc DRAM long-scoreboard
// stall that previously headed every step's FFMA2 chain in layer 1.
// LAYER==0 codegen is unchanged from R11.
// ---------------------------------------------------------------------------
#define SMEM_LSTM (32*256*16 /*Wsm*/ + 2*HID*4 /*h*/ + 2*G4*4 /*gates*/)

template<int LAYER>
__global__ void __launch_bounds__(256, 1)
lstm_kernel(const float* __restrict__ x,     // layer0: [B,T,1]
            const float* __restrict__ W_ih,  // layer0: [512,1]
            const float* __restrict__ W_hh,  // [512,128]
            const float* __restrict__ b_ih,
            const float* __restrict__ b_hh,
            const float* __restrict__ W_fc,  // layer1: [1,128]
            const float* __restrict__ b_fc,  // layer1: [1]
            float* __restrict__ out)
{
    ulonglong2* Wsm    = (ulonglong2*)dynsm;            // [32][256]
    float*      h_sm   = (float*)(dynsm + 32*256*16);   // [2][128]
    float*      gate_sm= h_sm + 2 * HID;                // [2][512]

    const int tid = threadIdx.x;
    const int b0  = blockIdx.x * 2;
    const int r0  = tid;
    const int r1  = 256 + tid;

    // ---- weight staging: row r0 -> smem (k-major), row r1 -> registers ----
    const ulonglong2* w0p = (const ulonglong2*)(W_hh + (size_t)r0 * HID);
    const ulonglong2* w1p = (const ulonglong2*)(W_hh + (size_t)r1 * HID);
    ulonglong2 wreg[32];
    #pragma unroll
    for (int j = 0; j < 32; j++) {
        Wsm[j * 256 + tid] = w0p[j];
        wreg[j] = w1p[j];
    }

    float wih0 = 0.f, wih1 = 0.f, bias0 = 0.f, bias1 = 0.f;
    if (LAYER == 0) {
        wih0  = __ldg(&W_ih[r0]);
        wih1  = __ldg(&W_ih[r1]);
        bias0 = __ldg(&b_ih[r0]) + __ldg(&b_hh[r0]);
        bias1 = __ldg(&b_ih[r1]) + __ldg(&b_hh[r1]);
    }

    h_sm[tid] = 0.f;           // tid covers [0, 2*HID)
    float c = 0.f;             // cell state: thread owns (ub, uj)
    __syncthreads();

    const ulonglong2* hp0 = (const ulonglong2*)h_sm;          // 32 chunks
    const ulonglong2* hp1 = (const ulonglong2*)(h_sm + HID);
    const int ub = tid >> 7;           // batch slot 0/1
    const int uj = tid & (HID - 1);    // hidden index

    // ---- LAYER 1: prefetch pipeline registers, seeded with xg(0) ----
    float nx00, nx01, nx10, nx11;
    if (LAYER == 1) {
        const float* p0 = g_xg1 + (size_t)b0 * TT * G4;
        const float* p1 = g_xg1 + (size_t)(b0 + 1) * TT * G4;
        nx00 = __ldg(p0 + r0);
        nx01 = __ldg(p1 + r0);
        nx10 = __ldg(p0 + r1);
        nx11 = __ldg(p1 + r1);
    }

    for (int t = 0; t < TT; t++) {
        // --- input-gate contributions for (row, batch) pairs ---
        float xg00, xg01, xg10, xg11;
        if (LAYER == 0) {
            float xv0 = __ldg(&x[(size_t)b0 * TT + t]);
            float xv1 = __ldg(&x[(size_t)(b0 + 1) * TT + t]);
            xg00 = fmaf(wih0, xv0, bias0);
            xg01 = fmaf(wih0, xv1, bias0);
            xg10 = fmaf(wih1, xv0, bias1);
            xg11 = fmaf(wih1, xv1, bias1);
        } else {
            // current values came from the prefetch pipeline
            xg00 = nx00; xg01 = nx01; xg10 = nx10; xg11 = nx11;
            // prefetch xg(t+1): LDGs overlap the whole dot below
            const int tn = (t + 1 < TT) ? t + 1 : t;
            const float* p0 = g_xg1 + ((size_t)b0 * TT + tn) * G4;
            const float* p1 = g_xg1 + ((size_t)(b0 + 1) * TT + tn) * G4;
            nx00 = __ldg(p0 + r0);
            nx01 = __ldg(p1 + r0);
            nx10 = __ldg(p0 + r1);
            nx11 = __ldg(p1 + r1);
        }

        // --- 4 dots of length 128, K-packed f32x2, 2 chains each ---
        // LAYER 0: seed with xg (unchanged, measured-good).
        // LAYER 1: seed 0, add xg post-dot (breaks LDG->FFMA2 chain).
        ull a00a = (LAYER == 0) ? pk2(xg00, 0.f) : pk2(0.f, 0.f), a00b = pk2(0.f, 0.f);
        ull a01a = (LAYER == 0) ? pk2(xg01, 0.f) : pk2(0.f, 0.f), a01b = pk2(0.f, 0.f);
        ull a10a = (LAYER == 0) ? pk2(xg10, 0.f) : pk2(0.f, 0.f), a10b = pk2(0.f, 0.f);
        ull a11a = (LAYER == 0) ? pk2(xg11, 0.f) : pk2(0.f, 0.f), a11b = pk2(0.f, 0.f);

        #pragma unroll
        for (int j = 0; j < 32; j++) {
            ulonglong2 wA = Wsm[j * 256 + tid];   // row r0 weights (smem)
            ulonglong2 h0 = hp0[j];               // broadcast
            ulonglong2 h1 = hp1[j];               // broadcast
            ulonglong2 wB = wreg[j];              // row r1 weights (regs)
            ffma2(a00a, wA.x, h0.x); ffma2(a00b, wA.y, h0.y);
            ffma2(a01a, wA.x, h1.x); ffma2(a01b, wA.y, h1.y);
            ffma2(a10a, wB.x, h0.x); ffma2(a10b, wB.y, h0.y);
            ffma2(a11a, wB.x, h1.x); ffma2(a11b, wB.y, h1.y);
        }

        float2 f;
        f = upk(a00a); float a00 = f.x + f.y; f = upk(a00b); a00 += f.x + f.y;
        f = upk(a01a); float a01 = f.x + f.y; f = upk(a01b); a01 += f.x + f.y;
        f = upk(a10a); float a10 = f.x + f.y; f = upk(a10b); a10 += f.x + f.y;
        f = upk(a11a); float a11 = f.x + f.y; f = upk(a11b); a11 += f.x + f.y;
        if (LAYER == 1) {
            a00 += xg00; a01 += xg01; a10 += xg10; a11 += xg11;
        }

        // --- activations: r0 is i (tid<128) or f -> sigmoid;
        //                  r1 is g (tid<128) -> tanh, else o -> sigmoid ---
        float g00 = sigm_f(a00);
        float g01 = sigm_f(a01);
        float g10, g11;
        if (tid < 128) { g10 = tanh_f(a10); g11 = tanh_f(a11); }
        else           { g10 = sigm_f(a10); g11 = sigm_f(a11); }

        gate_sm[r0]      = g00;
        gate_sm[G4 + r0] = g01;
        gate_sm[r1]      = g10;
        gate_sm[G4 + r1] = g11;
        __syncthreads();

        // --- cell/hidden update: all 256 threads, thread owns (ub, uj) ---
        {
            const float* gb = gate_sm + ub * G4;
            float iv = gb[uj];
            float fv = gb[HID + uj];
            float gv = gb[2 * HID + uj];
            float ov = gb[3 * HID + uj];
            c = fmaf(fv, c, iv * gv);
            float h = ov * tanh_f(c);
            h_sm[tid] = h;                         // tid == ub*HID + uj
            if (LAYER == 0)
                g_out0[((size_t)(b0 + ub) * TT + t) * HID + uj] = h;
        }
        __syncthreads();
    }

    // --- final h_n / c_n. out layout: y[256] | h_n[2][256][128] | c_n[2][256][128]
    {
        int bglob = b0 + ub;
        out[256 + ((size_t)LAYER * BATCH + bglob) * HID + uj] = h_sm[tid];
        out[256 + (size_t)2 * BATCH * HID
                + ((size_t)LAYER * BATCH + bglob) * HID + uj] = c;
    }

    // --- FC head (layer 1 only): y[b] = h_final[b] . W_fc + b_fc ---
    if (LAYER == 1 && tid < 64) {
        int w = tid >> 5;          // batch slot 0/1
        int l = tid & 31;
        float s = 0.f;
        #pragma unroll
        for (int j = l; j < HID; j += 32)
            s = fmaf(h_sm[w * HID + j], __ldg(&W_fc[j]), s);
        #pragma unroll
        for (int off = 16; off > 0; off >>= 1)
            s += __shfl_down_sync(0xffffffffu, s, off);
        if (l == 0)
            out[b0 + w] = s + __ldg(&b_fc[0]);
    }
}

// ---------------------------------------------------------------------------
// tf32 tensor-core GEMM (unchanged from R11, correctness-verified):
// g_xg1[M,512] = g_out0[M,128] @ W_ih1^T + bias
// ---------------------------------------------------------------------------
#define ASW_U (16*8*32*4)     // 16384 uints
#define BSW_U (16*32*20)      // 10240 uints
#define SMEM_GEMM ((ASW_U + BSW_U + 64) * 4)   // 106752 B

__global__ void __launch_bounds__(256, 2)
gemm_xg1_kernel(const float* __restrict__ W,     // W_ih_l1 [512,128]
                const float* __restrict__ b_ih,
                const float* __restrict__ b_hh)
{
    uint32_t* Asw    = (uint32_t*)dynsm;
    uint32_t* Bsw    = Asw + ASW_U;
    float*    bias_s = (float*)(Bsw + BSW_U);

    const int tid = threadIdx.x;
    const int n0  = blockIdx.x * 64;
    const int m0  = blockIdx.y * 128;

    if (tid < 64)
        bias_s[tid] = __ldg(&b_ih[n0 + tid]) + __ldg(&b_hh[n0 + tid]);

    // ---- stage A (128m x 128k): row-major global -> fragment order ----
    {
        const int row = tid >> 1;             // 0..127
        const int kh  = (tid & 1) * 64;       // k half
        const int w   = row >> 4;
        const int g   = row & 7;
        const int rb  = (row >> 3) & 1;       // row g vs g+8 within m16 tile
        const float4* ap = (const float4*)(g_out0 + (size_t)(m0 + row) * HID + kh);
        #pragma unroll
        for (int q = 0; q < 16; q++) {
            float4 v = ap[q];
            int k  = kh + q * 4;
            int s  = k >> 3;
            int kb = (k >> 2) & 1;
            uint32_t* dst = &Asw[(((s * 8 + w) * 32) + g * 4) * 4 + (rb + kb * 2)];
            dst[0]  = cvt_tf32(v.x);
            dst[4]  = cvt_tf32(v.y);
            dst[8]  = cvt_tf32(v.z);
            dst[12] = cvt_tf32(v.w);
        }
    }
    // ---- stage B (64n x 128k): W rows n0..n0+63 -> fragment order ----
    {
        const int bn  = tid & 63;             // n row
        const int kh  = (tid >> 6) * 32;      // k segment of 32
        const int nt  = bn >> 3;
        const int gg  = bn & 7;
        const float4* bp = (const float4*)(W + (size_t)(n0 + bn) * HID + kh);
        #pragma unroll
        for (int q = 0; q < 8; q++) {
            float4 v = bp[q];
            int k  = kh + q * 4;
            int s  = k >> 3;
            int kb = (k >> 2) & 1;
            uint32_t* dst = &Bsw[(s * 32 + gg * 4) * 20 + nt * 2 + kb];
            dst[0]  = cvt_tf32(v.x);
            dst[20] = cvt_tf32(v.y);
            dst[40] = cvt_tf32(v.z);
            dst[60] = cvt_tf32(v.w);
        }
    }
    __syncthreads();

    // ---- compute: warp w, lane l ----
    const int w = tid >> 5;
    const int l = tid & 31;

    float acc[8][4];
    #pragma unroll
    for (int i = 0; i < 8; i++)
        #pragma unroll
        for (int j = 0; j < 4; j++) acc[i][j] = 0.f;

    #pragma unroll
    for (int s = 0; s < 16; s++) {
        uint4 a = *(const uint4*)&Asw[((s * 8 + w) * 32 + l) * 4];
        const uint32_t* bb = &Bsw[(s * 32 + l) * 20];
        uint4 b0 = *(const uint4*)(bb + 0);
        uint4 b1 = *(const uint4*)(bb + 4);
        uint4 b2 = *(const uint4*)(bb + 8);
        uint4 b3 = *(const uint4*)(bb + 12);
        mma_tf32(acc[0], a, b0.x, b0.y); mma_tf32(acc[1], a, b0.z, b0.w);
        mma_tf32(acc[2], a, b1.x, b1.y); mma_tf32(acc[3], a, b1.z, b1.w);
        mma_tf32(acc[4], a, b2.x, b2.y); mma_tf32(acc[5], a, b2.z, b2.w);
        mma_tf32(acc[6], a, b3.x, b3.y); mma_tf32(acc[7], a, b3.z, b3.w);
    }

    // ---- epilogue ----
    const int g   = l >> 2;
    const int tig = l & 3;
    const size_t row0 = (size_t)(m0 + w * 16 + g);
    #pragma unroll
    for (int nt = 0; nt < 8; nt++) {
        int colb = nt * 8 + tig * 2;
        float bv0 = bias_s[colb], bv1 = bias_s[colb + 1];
        *(float2*)&g_xg1[row0 * G4 + n0 + colb] =
            make_float2(acc[nt][0] + bv0, acc[nt][1] + bv1);
        *(float2*)&g_xg1[(row0 + 8) * G4 + n0 + colb] =
            make_float2(acc[nt][2] + bv0, acc[nt][3] + bv1);
    }
}

// ---------------------------------------------------------------------------
// Launch
// ---------------------------------------------------------------------------
extern "C" void kernel_launch(void* const* d_in, const int* in_sizes, int n_in,
                              void* d_out, int out_size)
{
    const float* x      = (const float*)d_in[0];   // [256,2048,1]
    const float* W_ih0  = (const float*)d_in[1];   // [512,1]
    const float* W_hh0  = (const float*)d_in[2];   // [512,128]
    const float* b_ih0  = (const float*)d_in[3];
    const float* b_hh0  = (const float*)d_in[4];
    const float* W_ih1  = (const float*)d_in[5];   // [512,128]
    const float* W_hh1  = (const float*)d_in[6];   // [512,128]
    const float* b_ih1  = (const float*)d_in[7];
    const float* b_hh1  = (const float*)d_in[8];
    const float* W_fc   = (const float*)d_in[9];   // [1,128]
    const float* b_fc   = (const float*)d_in[10];  // [1]
    float* out = (float*)d_out;

    cudaFuncSetAttribute(lstm_kernel<0>, cudaFuncAttributeMaxDynamicSharedMemorySize, SMEM_LSTM);
    cudaFuncSetAttribute(lstm_kernel<1>, cudaFuncAttributeMaxDynamicSharedMemorySize, SMEM_LSTM);
    cudaFuncSetAttribute(gemm_xg1_kernel, cudaFuncAttributeMaxDynamicSharedMemorySize, SMEM_GEMM);

    // Layer 0 recurrence (writes g_out0, h_n[0], c_n[0])
    lstm_kernel<0><<<BATCH/2, 256, SMEM_LSTM>>>(
        x, W_ih0, W_hh0, b_ih0, b_hh0, nullptr, nullptr, out);

    // Layer 1 input gates: g_xg1 = g_out0 @ W_ih1^T + bias  (tf32 tensor cores)
    {
        dim3 grid(G4 / 64, MROWS / 128);
        gemm_xg1_kernel<<<grid, 256, SMEM_GEMM>>>(W_ih1, b_ih1, b_hh1);
    }

    // Layer 1 recurrence (reads g_xg1; writes h_n[1], c_n[1], y)
    lstm_kernel<1><<<BATCH/2, 256, SMEM_LSTM>>>(
        nullptr, nullptr, W_hh1, b_ih1, b_hh1, W_fc, b_fc, out);
}

// round 14
// speedup vs baseline: 1.3848x; 1.1574x over previous
#include <cuda_runtime.h>
#include <cuda_bf16.h>
#include <cstddef>
#include <stdint.h>
#include <math.h>

#define BATCH 256
#define TT    2048
#define HID   128
#define G4    512           // 4*HID
#define MROWS (BATCH*TT)    // 524288

typedef unsigned long long ull;

// ---- scratch (static device arrays: sanctioned allocation-free path) ----
__device__ float    g_out0[(size_t)MROWS * HID];   // layer0 hidden states [B*T, 128]
__device__ float    g_xg1 [(size_t)MROWS * G4];    // layer1 input gates (+bias) [B*T, 512]
__device__ uint32_t g_Bfrag[8 * 16 * 32 * 16];     // W_ih1 tf32 fragments [nb][s][lane][16]

// ---------------- packed f32x2 helpers (sm_103a) ----------------
__device__ __forceinline__ ull pk2(float lo, float hi) {
    ull r; asm("mov.b64 %0, {%1, %2};" : "=l"(r) : "f"(lo), "f"(hi)); return r;
}
__device__ __forceinline__ float2 upk(ull v) {
    float2 r; asm("mov.b64 {%0, %1}, %2;" : "=f"(r.x), "=f"(r.y) : "l"(v)); return r;
}
__device__ __forceinline__ void ffma2(ull& d, ull a, ull b) {
    asm("fma.rn.f32x2 %0, %1, %2, %0;" : "+l"(d) : "l"(a), "l"(b));
}

// ---------------- fast activations ----------------
__device__ __forceinline__ float sigm_f(float v) {
    float e = __expf(-v);
    return __fdividef(1.0f, 1.0f + e);    // inf -> 0, 0 -> 1 : correct tails
}
__device__ __forceinline__ float tanh_f(float v) {
    float e = __expf(2.0f * v);           // 0 -> -1, inf -> +1 : correct tails
    return 1.0f - __fdividef(2.0f, 1.0f + e);
}

// ---------------- tf32 helpers ----------------
__device__ __forceinline__ uint32_t cvt_tf32(float f) {
    uint32_t r; asm("cvt.rna.tf32.f32 %0, %1;" : "=r"(r) : "f"(f)); return r;
}
__device__ __forceinline__ void mma_tf32(float* c, uint4 a, uint32_t b0, uint32_t b1) {
    asm volatile("mma.sync.aligned.m16n8k8.row.col.f32.tf32.tf32.f32 "
        "{%0,%1,%2,%3}, {%4,%5,%6,%7}, {%8,%9}, {%0,%1,%2,%3};"
        : "+f"(c[0]), "+f"(c[1]), "+f"(c[2]), "+f"(c[3])
        : "r"(a.x), "r"(a.y), "r"(a.z), "r"(a.w), "r"(b0), "r"(b1));
}

extern __shared__ __align__(16) unsigned char dynsm[];

// ---------------------------------------------------------------------------
// LSTM layer — R13 (measured 2715us layer 0; layer 1 with xg prefetch).
// ---------------------------------------------------------------------------
#define SMEM_LSTM (32*256*16 /*Wsm*/ + 2*HID*4 /*h*/ + 2*G4*4 /*gates*/)

template<int LAYER>
__global__ void __launch_bounds__(256, 1)
lstm_kernel(const float* __restrict__ x,     // layer0: [B,T,1]
            const float* __restrict__ W_ih,  // layer0: [512,1]
            const float* __restrict__ W_hh,  // [512,128]
            const float* __restrict__ b_ih,
            const float* __restrict__ b_hh,
            const float* __restrict__ W_fc,  // layer1: [1,128]
            const float* __restrict__ b_fc,  // layer1: [1]
            float* __restrict__ out)
{
    ulonglong2* Wsm    = (ulonglong2*)dynsm;            // [32][256]
    float*      h_sm   = (float*)(dynsm + 32*256*16);   // [2][128]
    float*      gate_sm= h_sm + 2 * HID;                // [2][512]

    const int tid = threadIdx.x;
    const int b0  = blockIdx.x * 2;
    const int r0  = tid;
    const int r1  = 256 + tid;

    // ---- weight staging: row r0 -> smem (k-major), row r1 -> registers ----
    const ulonglong2* w0p = (const ulonglong2*)(W_hh + (size_t)r0 * HID);
    const ulonglong2* w1p = (const ulonglong2*)(W_hh + (size_t)r1 * HID);
    ulonglong2 wreg[32];
    #pragma unroll
    for (int j = 0; j < 32; j++) {
        Wsm[j * 256 + tid] = w0p[j];
        wreg[j] = w1p[j];
    }

    float wih0 = 0.f, wih1 = 0.f, bias0 = 0.f, bias1 = 0.f;
    if (LAYER == 0) {
        wih0  = __ldg(&W_ih[r0]);
        wih1  = __ldg(&W_ih[r1]);
        bias0 = __ldg(&b_ih[r0]) + __ldg(&b_hh[r0]);
        bias1 = __ldg(&b_ih[r1]) + __ldg(&b_hh[r1]);
    }

    h_sm[tid] = 0.f;           // tid covers [0, 2*HID)
    float c = 0.f;             // cell state: thread owns (ub, uj)
    __syncthreads();

    const ulonglong2* hp0 = (const ulonglong2*)h_sm;          // 32 chunks
    const ulonglong2* hp1 = (const ulonglong2*)(h_sm + HID);
    const int ub = tid >> 7;           // batch slot 0/1
    const int uj = tid & (HID - 1);    // hidden index

    // ---- LAYER 1: prefetch pipeline registers, seeded with xg(0) ----
    float nx00, nx01, nx10, nx11;
    if (LAYER == 1) {
        const float* p0 = g_xg1 + (size_t)b0 * TT * G4;
        const float* p1 = g_xg1 + (size_t)(b0 + 1) * TT * G4;
        nx00 = __ldg(p0 + r0);
        nx01 = __ldg(p1 + r0);
        nx10 = __ldg(p0 + r1);
        nx11 = __ldg(p1 + r1);
    }

    for (int t = 0; t < TT; t++) {
        float xg00, xg01, xg10, xg11;
        if (LAYER == 0) {
            float xv0 = __ldg(&x[(size_t)b0 * TT + t]);
            float xv1 = __ldg(&x[(size_t)(b0 + 1) * TT + t]);
            xg00 = fmaf(wih0, xv0, bias0);
            xg01 = fmaf(wih0, xv1, bias0);
            xg10 = fmaf(wih1, xv0, bias1);
            xg11 = fmaf(wih1, xv1, bias1);
        } else {
            xg00 = nx00; xg01 = nx01; xg10 = nx10; xg11 = nx11;
            const int tn = (t + 1 < TT) ? t + 1 : t;
            const float* p0 = g_xg1 + ((size_t)b0 * TT + tn) * G4;
            const float* p1 = g_xg1 + ((size_t)(b0 + 1) * TT + tn) * G4;
            nx00 = __ldg(p0 + r0);
            nx01 = __ldg(p1 + r0);
            nx10 = __ldg(p0 + r1);
            nx11 = __ldg(p1 + r1);
        }

        ull a00a = (LAYER == 0) ? pk2(xg00, 0.f) : pk2(0.f, 0.f), a00b = pk2(0.f, 0.f);
        ull a01a = (LAYER == 0) ? pk2(xg01, 0.f) : pk2(0.f, 0.f), a01b = pk2(0.f, 0.f);
        ull a10a = (LAYER == 0) ? pk2(xg10, 0.f) : pk2(0.f, 0.f), a10b = pk2(0.f, 0.f);
        ull a11a = (LAYER == 0) ? pk2(xg11, 0.f) : pk2(0.f, 0.f), a11b = pk2(0.f, 0.f);

        #pragma unroll
        for (int j = 0; j < 32; j++) {
            ulonglong2 wA = Wsm[j * 256 + tid];
            ulonglong2 h0 = hp0[j];
            ulonglong2 h1 = hp1[j];
            ulonglong2 wB = wreg[j];
            ffma2(a00a, wA.x, h0.x); ffma2(a00b, wA.y, h0.y);
            ffma2(a01a, wA.x, h1.x); ffma2(a01b, wA.y, h1.y);
            ffma2(a10a, wB.x, h0.x); ffma2(a10b, wB.y, h0.y);
            ffma2(a11a, wB.x, h1.x); ffma2(a11b, wB.y, h1.y);
        }

        float2 f;
        f = upk(a00a); float a00 = f.x + f.y; f = upk(a00b); a00 += f.x + f.y;
        f = upk(a01a); float a01 = f.x + f.y; f = upk(a01b); a01 += f.x + f.y;
        f = upk(a10a); float a10 = f.x + f.y; f = upk(a10b); a10 += f.x + f.y;
        f = upk(a11a); float a11 = f.x + f.y; f = upk(a11b); a11 += f.x + f.y;
        if (LAYER == 1) {
            a00 += xg00; a01 += xg01; a10 += xg10; a11 += xg11;
        }

        float g00 = sigm_f(a00);
        float g01 = sigm_f(a01);
        float g10, g11;
        if (tid < 128) { g10 = tanh_f(a10); g11 = tanh_f(a11); }
        else           { g10 = sigm_f(a10); g11 = sigm_f(a11); }

        gate_sm[r0]      = g00;
        gate_sm[G4 + r0] = g01;
        gate_sm[r1]      = g10;
        gate_sm[G4 + r1] = g11;
        __syncthreads();

        {
            const float* gb = gate_sm + ub * G4;
            float iv = gb[uj];
            float fv = gb[HID + uj];
            float gv = gb[2 * HID + uj];
            float ov = gb[3 * HID + uj];
            c = fmaf(fv, c, iv * gv);
            float h = ov * tanh_f(c);
            h_sm[tid] = h;
            if (LAYER == 0)
                g_out0[((size_t)(b0 + ub) * TT + t) * HID + uj] = h;
        }
        __syncthreads();
    }

    {
        int bglob = b0 + ub;
        out[256 + ((size_t)LAYER * BATCH + bglob) * HID + uj] = h_sm[tid];
        out[256 + (size_t)2 * BATCH * HID
                + ((size_t)LAYER * BATCH + bglob) * HID + uj] = c;
    }

    if (LAYER == 1 && tid < 64) {
        int w = tid >> 5;
        int l = tid & 31;
        float s = 0.f;
        #pragma unroll
        for (int j = l; j < HID; j += 32)
            s = fmaf(h_sm[w * HID + j], __ldg(&W_fc[j]), s);
        #pragma unroll
        for (int off = 16; off > 0; off >>= 1)
            s += __shfl_down_sync(0xffffffffu, s, off);
        if (l == 0)
            out[b0 + w] = s + __ldg(&b_fc[0]);
    }
}

// ---------------------------------------------------------------------------
// B-fragment precompute: W_ih1 [512,128] -> tf32 mma fragments in global.
// Layout: g_Bfrag[((nb*16+s)*32+l)*16 + nt*2 + kb], value =
//   cvt_tf32(W[nb*64 + nt*8 + (l>>2)][8s + (l&3) + 4*kb]).
// One-time tiny kernel (4096 threads). L2-resident; shared by all m-tiles.
// ---------------------------------------------------------------------------
__global__ void __launch_bounds__(256)
bfrag_kernel(const float* __restrict__ W)
{
    const int id = blockIdx.x * 256 + threadIdx.x;   // 0..4095
    const int nb = id >> 9;
    const int rem = id & 511;
    const int s  = rem >> 5;
    const int l  = rem & 31;
    const int gp = l >> 2;       // n within 8
    const int tg = l & 3;        // k within 4

    uint32_t* dst = g_Bfrag + (size_t)id * 16;
    #pragma unroll
    for (int nt = 0; nt < 8; nt++) {
        const float* wr = W + (size_t)(nb * 64 + nt * 8 + gp) * HID + s * 8 + tg;
        dst[nt * 2 + 0] = cvt_tf32(__ldg(wr));
        dst[nt * 2 + 1] = cvt_tf32(__ldg(wr + 4));
    }
}

// ---------------------------------------------------------------------------
// tf32 tensor-core GEMM v2: g_xg1[M,512] = g_out0[M,128] @ W_ih1^T + bias.
// CTA 256 thr / 8 warps; tile 128m x 64n, K=128 single pass. 2 CTAs/SM.
// A: row-major smem [128][132] (pad 132 -> fragment LDS.32 banks (4g+tig)%32
//    bijective = conflict-free; staging = linear LDG.128 + conflict-free STS.128,
//    tf32-converted at staging).
// B: precomputed fragments copied linearly from g_Bfrag into stride-20 regions
//    (conflict-free STS.128; reads = R11-verified stride-20 uint4, conflict-free
//    in 8-lane phases).
// Hot loop per warp per k-step: 4 LDS.32 + 4 LDS.128 + 8 HMMA. No conflicts.
// ---------------------------------------------------------------------------
#define AT_LD 132
#define BF_STRIDE 20
#define AT_U   (128*AT_LD)          // 16896 uints
#define BF_U   (16*32*BF_STRIDE)    // 10240 uints
#define SMEM_GEMM ((AT_U + BF_U + 64) * 4)   // 108,800 B

__global__ void __launch_bounds__(256, 2)
gemm_xg1_kernel(const float* __restrict__ b_ih,
                const float* __restrict__ b_hh)
{
    uint32_t* At     = (uint32_t*)dynsm;          // [128][132] tf32
    uint32_t* Bf     = At + AT_U;                 // [16*32][20]
    float*    bias_s = (float*)(Bf + BF_U);

    const int tid = threadIdx.x;
    const int nb  = blockIdx.x;          // n-block 0..7
    const int n0  = nb * 64;
    const int m0  = blockIdx.y * 128;

    if (tid < 64)
        bias_s[tid] = __ldg(&b_ih[n0 + tid]) + __ldg(&b_hh[n0 + tid]);

    // ---- stage A: linear-coalesced LDG.128, cvt, conflict-free STS.128 ----
    {
        const float4* src = (const float4*)(g_out0 + (size_t)m0 * HID);
        #pragma unroll
        for (int it = 0; it < 16; it++) {
            int fi = (it * 256 + tid);            // float4 index 0..4095
            float4 v = __ldg(&src[fi]);
            int row = (fi * 4) >> 7;              // warp-uniform row
            int col = (fi * 4) & 127;
            uint4 u = make_uint4(cvt_tf32(v.x), cvt_tf32(v.y),
                                 cvt_tf32(v.z), cvt_tf32(v.w));
            *(uint4*)&At[row * AT_LD + col] = u;
        }
    }
    // ---- stage B: linear copy of precomputed fragments (conflict-free) ----
    {
        #pragma unroll
        for (int h = 0; h < 2; h++) {
            int rr = h * 256 + tid;               // region 0..511 = s*32+l
            const uint4* src = (const uint4*)(g_Bfrag + ((size_t)nb * 512 + rr) * 16);
            uint32_t* dst = &Bf[rr * BF_STRIDE];
            uint4 v0 = __ldg(&src[0]);
            uint4 v1 = __ldg(&src[1]);
            uint4 v2 = __ldg(&src[2]);
            uint4 v3 = __ldg(&src[3]);
            *(uint4*)(dst + 0)  = v0;
            *(uint4*)(dst + 4)  = v1;
            *(uint4*)(dst + 8)  = v2;
            *(uint4*)(dst + 12) = v3;
        }
    }
    __syncthreads();

    // ---- compute: warp w owns m rows [16w,16w+16); lane l ----
    const int w = tid >> 5;
    const int l = tid & 31;
    const int g  = l >> 2;
    const int tg = l & 3;
    const uint32_t* arow0 = &At[(16 * w + g) * AT_LD];       // row g
    const uint32_t* arow8 = &At[(16 * w + g + 8) * AT_LD];   // row g+8

    float acc[8][4];
    #pragma unroll
    for (int i = 0; i < 8; i++)
        #pragma unroll
        for (int j = 0; j < 4; j++) acc[i][j] = 0.f;

    #pragma unroll
    for (int s = 0; s < 16; s++) {
        uint4 a;
        a.x = arow0[s * 8 + tg];        // banks (4g+tg)%32: bijective, CF
        a.y = arow8[s * 8 + tg];
        a.z = arow0[s * 8 + tg + 4];
        a.w = arow8[s * 8 + tg + 4];
        const uint32_t* bb = &Bf[(s * 32 + l) * BF_STRIDE];
        uint4 b0 = *(const uint4*)(bb + 0);
        uint4 b1 = *(const uint4*)(bb + 4);
        uint4 b2 = *(const uint4*)(bb + 8);
        uint4 b3 = *(const uint4*)(bb + 12);
        mma_tf32(acc[0], a, b0.x, b0.y); mma_tf32(acc[1], a, b0.z, b0.w);
        mma_tf32(acc[2], a, b1.x, b1.y); mma_tf32(acc[3], a, b1.z, b1.w);
        mma_tf32(acc[4], a, b2.x, b2.y); mma_tf32(acc[5], a, b2.z, b2.w);
        mma_tf32(acc[6], a, b3.x, b3.y); mma_tf32(acc[7], a, b3.z, b3.w);
    }

    // ---- epilogue (R11-verified mapping) ----
    const size_t row0 = (size_t)(m0 + w * 16 + g);
    #pragma unroll
    for (int nt = 0; nt < 8; nt++) {
        int colb = nt * 8 + tg * 2;
        float bv0 = bias_s[colb], bv1 = bias_s[colb + 1];
        *(float2*)&g_xg1[row0 * G4 + n0 + colb] =
            make_float2(acc[nt][0] + bv0, acc[nt][1] + bv1);
        *(float2*)&g_xg1[(row0 + 8) * G4 + n0 + colb] =
            make_float2(acc[nt][2] + bv0, acc[nt][3] + bv1);
    }
}

// ---------------------------------------------------------------------------
// Launch
// ---------------------------------------------------------------------------
extern "C" void kernel_launch(void* const* d_in, const int* in_sizes, int n_in,
                              void* d_out, int out_size)
{
    const float* x      = (const float*)d_in[0];   // [256,2048,1]
    const float* W_ih0  = (const float*)d_in[1];   // [512,1]
    const float* W_hh0  = (const float*)d_in[2];   // [512,128]
    const float* b_ih0  = (const float*)d_in[3];
    const float* b_hh0  = (const float*)d_in[4];
    const float* W_ih1  = (const float*)d_in[5];   // [512,128]
    const float* W_hh1  = (const float*)d_in[6];   // [512,128]
    const float* b_ih1  = (const float*)d_in[7];
    const float* b_hh1  = (const float*)d_in[8];
    const float* W_fc   = (const float*)d_in[9];   // [1,128]
    const float* b_fc   = (const float*)d_in[10];  // [1]
    float* out = (float*)d_out;

    cudaFuncSetAttribute(lstm_kernel<0>, cudaFuncAttributeMaxDynamicSharedMemorySize, SMEM_LSTM);
    cudaFuncSetAttribute(lstm_kernel<1>, cudaFuncAttributeMaxDynamicSharedMemorySize, SMEM_LSTM);
    cudaFuncSetAttribute(gemm_xg1_kernel, cudaFuncAttributeMaxDynamicSharedMemorySize, SMEM_GEMM);

    // B fragments (independent of layer-0 output; overlaps lstm<0> tail)
    bfrag_kernel<<<16, 256>>>(W_ih1);

    // Layer 0 recurrence (writes g_out0, h_n[0], c_n[0])
    lstm_kernel<0><<<BATCH/2, 256, SMEM_LSTM>>>(
        x, W_ih0, W_hh0, b_ih0, b_hh0, nullptr, nullptr, out);

    // Layer 1 input gates: g_xg1 = g_out0 @ W_ih1^T + bias (tf32 tensor cores)
    {
        dim3 grid(G4 / 64, MROWS / 128);
        gemm_xg1_kernel<<<grid, 256, SMEM_GEMM>>>(b_ih1, b_hh1);
    }

    // Layer 1 recurrence (reads g_xg1; writes h_n[1], c_n[1], y)
    lstm_kernel<1><<<BATCH/2, 256, SMEM_LSTM>>>(
        nullptr, nullptr, W_hh1, b_ih1, b_hh1, W_fc, b_fc, out);
}